// round 1
// baseline (speedup 1.0000x reference)
#include <cuda_runtime.h>
#include <math.h>
#include <stddef.h>

// Problem dims
#define B_  64
#define T_  2048
#define I_  128
#define H_  256
#define G4  1024      // 4*H
#define C_  64

#define NGROUP 8      // batch groups (8 batches each)
#define GBLK   16     // blocks per group (u-tiles of 16)

// ---------------- scratch (static device allocations; no cudaMalloc) --------
__device__ float     g_xg   [(size_t)B_ * T_ * G4];   // 512 MB gate preacts
__device__ float     g_hseq [(size_t)B_ * T_ * H_];   // 128 MB layer-0 h sequence / y0
__device__ float     g_hbuf [2][B_ * H_];             // double-buffered h state
__device__ float     g_hfinal[B_ * H_];               // layer-1 final h
__device__ unsigned  g_bar  [NGROUP];                 // per-group barrier counters

// ---------------- helpers ---------------------------------------------------
__device__ __forceinline__ float sigm(float x) { return 1.0f / (1.0f + expf(-x)); }

// ---------------- init: zero barrier counters + h buffers -------------------
__global__ void init_kernel() {
    int i = blockIdx.x * blockDim.x + threadIdx.x;
    if (i < NGROUP) g_bar[i] = 0u;
    float* hb = &g_hbuf[0][0];
    int n = 2 * B_ * H_;
    for (int j = i; j < n; j += gridDim.x * blockDim.x) hb[j] = 0.0f;
}

// ---------------- phase A: xg = A @ W^T + (bih + bhh) -----------------------
// A: [M x K] row-major (M = B*T), W: [1024 x K] row-major, C = g_xg [M x 1024]
// Tiles: BM=128, BN=64, BK=16, 256 threads, thread tile 8x4.
template<int K, int USE_HSEQ>
__global__ void __launch_bounds__(256) sgemm_xg(const float* __restrict__ Ain,
                                                const float* __restrict__ W,
                                                const float* __restrict__ bih,
                                                const float* __restrict__ bhh)
{
    const float* A = USE_HSEQ ? (const float*)g_hseq : Ain;
    const int n0 = blockIdx.x * 64;
    const int m0 = blockIdx.y * 128;

    __shared__ float Ash[16][128];
    __shared__ float Bsh[16][64];

    const int tid = threadIdx.x;
    const int tx  = tid & 15;      // 0..15 -> col group (4 cols)
    const int ty  = tid >> 4;      // 0..15 -> row group (8 rows)

    float acc[8][4];
#pragma unroll
    for (int i = 0; i < 8; ++i)
#pragma unroll
        for (int j = 0; j < 4; ++j) acc[i][j] = 0.0f;

    const int lm = tid >> 2;        // 0..63
    const int lk = (tid & 3) * 4;   // 0,4,8,12

    for (int k0 = 0; k0 < K; k0 += 16) {
        float4 a0 = __ldg((const float4*)&A[(size_t)(m0 + lm)      * K + k0 + lk]);
        float4 a1 = __ldg((const float4*)&A[(size_t)(m0 + lm + 64) * K + k0 + lk]);
        float4 w0 = __ldg((const float4*)&W[(size_t)(n0 + lm)      * K + k0 + lk]);
        Ash[lk + 0][lm] = a0.x; Ash[lk + 1][lm] = a0.y; Ash[lk + 2][lm] = a0.z; Ash[lk + 3][lm] = a0.w;
        Ash[lk + 0][lm + 64] = a1.x; Ash[lk + 1][lm + 64] = a1.y; Ash[lk + 2][lm + 64] = a1.z; Ash[lk + 3][lm + 64] = a1.w;
        Bsh[lk + 0][lm] = w0.x; Bsh[lk + 1][lm] = w0.y; Bsh[lk + 2][lm] = w0.z; Bsh[lk + 3][lm] = w0.w;
        __syncthreads();

#pragma unroll
        for (int kk = 0; kk < 16; ++kk) {
            float4 av0 = *(const float4*)&Ash[kk][ty * 8];
            float4 av1 = *(const float4*)&Ash[kk][ty * 8 + 4];
            float4 bv  = *(const float4*)&Bsh[kk][tx * 4];
            float a[8] = {av0.x, av0.y, av0.z, av0.w, av1.x, av1.y, av1.z, av1.w};
            float bb[4] = {bv.x, bv.y, bv.z, bv.w};
#pragma unroll
            for (int i = 0; i < 8; ++i)
#pragma unroll
                for (int j = 0; j < 4; ++j)
                    acc[i][j] = fmaf(a[i], bb[j], acc[i][j]);
        }
        __syncthreads();
    }

    const int n = n0 + tx * 4;
    float bb0 = __ldg(&bih[n + 0]) + __ldg(&bhh[n + 0]);
    float bb1 = __ldg(&bih[n + 1]) + __ldg(&bhh[n + 1]);
    float bb2 = __ldg(&bih[n + 2]) + __ldg(&bhh[n + 2]);
    float bb3 = __ldg(&bih[n + 3]) + __ldg(&bhh[n + 3]);
#pragma unroll
    for (int i = 0; i < 8; ++i) {
        size_t m = (size_t)m0 + ty * 8 + i;
        float4 o = make_float4(acc[i][0] + bb0, acc[i][1] + bb1, acc[i][2] + bb2, acc[i][3] + bb3);
        *(float4*)&g_xg[m * G4 + n] = o;
    }
}

// ---------------- phase B: persistent recurrent scan ------------------------
// grid 128 blocks, 256 threads. block = (batch group of 8) x (u-tile of 16).
// Thread owns one gate row (of 64 in the tile) x one K-quarter (64 weights in regs).
// One inter-block barrier per step, scoped to the 16 blocks of the batch group.
template<int FINAL_ONLY>
__global__ void __launch_bounds__(256, 1) recur_kernel(const float* __restrict__ Whh,
                                                       const float* __restrict__ mask)
{
    const int blk = blockIdx.x;
    const int grp = blk >> 4;          // 0..7  batch group
    const int ib  = blk & 15;          // 0..15 u-tile
    const int B0  = grp * 8;
    const int u0  = ib * 16;
    const int tid = threadIdx.x;
    const int u_local = tid & 15;
    const int gate    = (tid >> 4) & 3;
    const int ksub    = tid >> 6;       // 0..3
    const int row     = gate * 256 + u0 + u_local;   // gate row in [0,1024)

    __shared__ float h_sh[8][256];
    __shared__ float part[4][512];      // [ksub][(gate*16+u)*8 + b]
    __shared__ float gs[512];

    // Load this thread's weight slice into registers (stays for all 2048 steps)
    float w[64];
    {
        const float4* wp = (const float4*)(Whh + (size_t)row * H_ + ksub * 64);
#pragma unroll
        for (int i = 0; i < 16; ++i) {
            float4 v = __ldg(wp + i);
            w[4*i] = v.x; w[4*i+1] = v.y; w[4*i+2] = v.z; w[4*i+3] = v.w;
        }
    }

    // stage-2 identity (threads < 128 own one (b,u) cell's c-state)
    const int b2 = tid >> 4;   // 0..7  (valid for tid < 128)
    const int u2 = tid & 15;
    float c_state = 0.0f;
    const float* maskp = mask + (size_t)(B0 + b2) * T_;

    // xg prefetch addressing (each thread reduces outputs s=tid and s=tid+256)
    const int sA = tid;
    const int gA = sA >> 7, uA = (sA >> 3) & 15, bA = sA & 7;
    const int sB = tid + 256;
    const int gB = sB >> 7, uB = (sB >> 3) & 15, bB = sB & 7;
    const float* xgA = g_xg + (size_t)(B0 + bA) * T_ * G4 + gA * 256 + u0 + uA;
    const float* xgB = g_xg + (size_t)(B0 + bB) * T_ * G4 + gB * 256 + u0 + uB;

    unsigned target = 0;
    volatile unsigned* barp = (volatile unsigned*)&g_bar[grp];

    for (int step = 0; step < T_; ++step) {
        const int rbuf = step & 1;

        // early independent loads (latency hidden behind the GEMM)
        float xa = __ldg(xgA + (size_t)step * G4);
        float xb = __ldg(xgB + (size_t)step * G4);

        // load h(t-1) for our 8 batches into smem (L1-bypassing: other SMs wrote it)
        {
            const float4* src = (const float4*)(g_hbuf[rbuf] + B0 * H_);
            float4* dst = (float4*)&h_sh[0][0];
            dst[tid]       = __ldcg(src + tid);
            dst[tid + 256] = __ldcg(src + tid + 256);
        }
        __syncthreads();

        // GEMM partial: acc[b] = sum_{k in ksub slice} w[k] * h[b][k]
        float acc[8];
#pragma unroll
        for (int b = 0; b < 8; ++b) acc[b] = 0.0f;
#pragma unroll
        for (int kc = 0; kc < 16; ++kc) {
#pragma unroll
            for (int b = 0; b < 8; ++b) {
                float4 hv = *(const float4*)&h_sh[b][ksub * 64 + kc * 4];
                acc[b] = fmaf(w[4*kc + 0], hv.x, acc[b]);
                acc[b] = fmaf(w[4*kc + 1], hv.y, acc[b]);
                acc[b] = fmaf(w[4*kc + 2], hv.z, acc[b]);
                acc[b] = fmaf(w[4*kc + 3], hv.w, acc[b]);
            }
        }
        {
            float* pp = &part[ksub][(gate * 16 + u_local) * 8];
#pragma unroll
            for (int b = 0; b < 8; ++b) pp[b] = acc[b];
        }
        __syncthreads();

        // K-split reduction + xg add
        gs[tid]       = part[0][tid]       + part[1][tid]       + part[2][tid]       + part[3][tid]       + xa;
        gs[tid + 256] = part[0][tid + 256] + part[1][tid + 256] + part[2][tid + 256] + part[3][tid + 256] + xb;
        __syncthreads();

        // gate nonlinearities + state update (128 threads: one per (b,u))
        if (tid < 128) {
            float gi = gs[( 0 + u2) * 8 + b2];
            float gf = gs[(16 + u2) * 8 + b2];
            float gg = gs[(32 + u2) * 8 + b2];
            float go = gs[(48 + u2) * 8 + b2];
            float c = sigm(gf) * c_state + sigm(gi) * tanhf(gg);
            float h = sigm(go) * tanhf(c);
            float m = __ldg(maskp + step);
            h *= m; c *= m;
            c_state = c;
            g_hbuf[rbuf ^ 1][(B0 + b2) * H_ + u0 + u2] = h;
            if (!FINAL_ONLY) {
                g_hseq[((size_t)(B0 + b2) * T_ + step) * H_ + u0 + u2] = h;
            } else if (step == T_ - 1) {
                g_hfinal[(B0 + b2) * H_ + u0 + u2] = h;
            }
        }

        // release + per-group barrier (16 blocks)
        __threadfence();
        __syncthreads();
        target += GBLK;
        if (tid == 0) {
            atomicAdd((unsigned*)&g_bar[grp], 1u);
            while (*barp < target) { }
        }
        __syncthreads();
    }
}

// ---------------- LN + ReLU over layer-0 output (in place) ------------------
__global__ void ln_relu_kernel(const float* __restrict__ g, const float* __restrict__ b)
{
    int row  = blockIdx.x * 8 + (threadIdx.x >> 5);
    int lane = threadIdx.x & 31;
    float* p = g_hseq + (size_t)row * H_;
    float4 v0 = *(float4*)(p + lane * 4);
    float4 v1 = *(float4*)(p + 128 + lane * 4);
    float s = v0.x + v0.y + v0.z + v0.w + v1.x + v1.y + v1.z + v1.w;
    float q = v0.x*v0.x + v0.y*v0.y + v0.z*v0.z + v0.w*v0.w
            + v1.x*v1.x + v1.y*v1.y + v1.z*v1.z + v1.w*v1.w;
#pragma unroll
    for (int o = 16; o; o >>= 1) {
        s += __shfl_xor_sync(0xffffffffu, s, o);
        q += __shfl_xor_sync(0xffffffffu, q, o);
    }
    float mu  = s * (1.0f / 256.0f);
    float var = q * (1.0f / 256.0f) - mu * mu;
    float rs  = rsqrtf(var + 1e-5f);
    int u = lane * 4;
    float4 G0 = *(const float4*)(g + u);       float4 Bb0 = *(const float4*)(b + u);
    float4 G1 = *(const float4*)(g + 128 + u); float4 Bb1 = *(const float4*)(b + 128 + u);
    v0.x = fmaxf(0.0f, (v0.x - mu) * rs * G0.x + Bb0.x);
    v0.y = fmaxf(0.0f, (v0.y - mu) * rs * G0.y + Bb0.y);
    v0.z = fmaxf(0.0f, (v0.z - mu) * rs * G0.z + Bb0.z);
    v0.w = fmaxf(0.0f, (v0.w - mu) * rs * G0.w + Bb0.w);
    v1.x = fmaxf(0.0f, (v1.x - mu) * rs * G1.x + Bb1.x);
    v1.y = fmaxf(0.0f, (v1.y - mu) * rs * G1.y + Bb1.y);
    v1.z = fmaxf(0.0f, (v1.z - mu) * rs * G1.z + Bb1.z);
    v1.w = fmaxf(0.0f, (v1.w - mu) * rs * G1.w + Bb1.w);
    *(float4*)(p + lane * 4)       = v0;
    *(float4*)(p + 128 + lane * 4) = v1;
}

// ---------------- final: LN + ReLU + FC on last-step h of layer 1 -----------
__global__ void final_kernel(const float* __restrict__ lng, const float* __restrict__ lnb,
                             const float* __restrict__ fcW, const float* __restrict__ fcb,
                             float* __restrict__ out)
{
    int b = blockIdx.x;
    int t = threadIdx.x;
    __shared__ float ssum[8], sq[8];
    __shared__ float y[256];
    __shared__ float stats[2];
    float v = g_hfinal[b * H_ + t];
    float s = v, q = v * v;
#pragma unroll
    for (int o = 16; o; o >>= 1) {
        s += __shfl_xor_sync(0xffffffffu, s, o);
        q += __shfl_xor_sync(0xffffffffu, q, o);
    }
    if ((t & 31) == 0) { ssum[t >> 5] = s; sq[t >> 5] = q; }
    __syncthreads();
    if (t == 0) {
        float S = 0.0f, Q = 0.0f;
        for (int i = 0; i < 8; ++i) { S += ssum[i]; Q += sq[i]; }
        float mu  = S * (1.0f / 256.0f);
        float var = Q * (1.0f / 256.0f) - mu * mu;
        stats[0] = mu;
        stats[1] = rsqrtf(var + 1e-5f);
    }
    __syncthreads();
    y[t] = fmaxf(0.0f, (v - stats[0]) * stats[1] * lng[t] + lnb[t]);
    __syncthreads();
    if (t < C_) {
        float a = fcb[t];
        const float* wr = fcW + (size_t)t * H_;
#pragma unroll 8
        for (int u = 0; u < H_; ++u) a = fmaf(y[u], wr[u], a);
        out[b * C_ + t] = a;
    }
}

// ---------------- host entry -------------------------------------------------
extern "C" void kernel_launch(void* const* d_in, const int* in_sizes, int n_in,
                              void* d_out, int out_size)
{
    const float* seq  = (const float*)d_in[0];
    const float* mask = (const float*)d_in[1];
    const float* Wih0 = (const float*)d_in[2];
    const float* Whh0 = (const float*)d_in[3];
    const float* bih0 = (const float*)d_in[4];
    const float* bhh0 = (const float*)d_in[5];
    const float* lng0 = (const float*)d_in[6];
    const float* lnb0 = (const float*)d_in[7];
    const float* Wih1 = (const float*)d_in[8];
    const float* Whh1 = (const float*)d_in[9];
    const float* bih1 = (const float*)d_in[10];
    const float* bhh1 = (const float*)d_in[11];
    const float* lng1 = (const float*)d_in[12];
    const float* lnb1 = (const float*)d_in[13];
    const float* fcW  = (const float*)d_in[14];
    const float* fcb  = (const float*)d_in[15];
    float* out = (float*)d_out;

    const int M = B_ * T_;               // 131072
    dim3 gemm_grid(G4 / 64, M / 128);    // (16, 1024)

    // ---- layer 0 ----
    init_kernel<<<32, 256>>>();
    sgemm_xg<I_, 0><<<gemm_grid, 256>>>(seq, Wih0, bih0, bhh0);
    recur_kernel<0><<<NGROUP * GBLK, 256>>>(Whh0, mask);
    ln_relu_kernel<<<M / 8, 256>>>(lng0, lnb0);

    // ---- layer 1 ----
    init_kernel<<<32, 256>>>();
    sgemm_xg<H_, 1><<<gemm_grid, 256>>>(nullptr, Wih1, bih1, bhh1);
    recur_kernel<1><<<NGROUP * GBLK, 256>>>(Whh1, mask);

    // ---- head ----
    final_kernel<<<B_, 256>>>(lng1, lnb1, fcW, fcb, out);
}

// round 3
// speedup vs baseline: 1.1945x; 1.1945x over previous
#include <cuda_runtime.h>
#include <math.h>
#include <stddef.h>

// Problem dims
#define B_  64
#define T_  2048
#define I_  128
#define H_  256
#define G4  1024      // 4*H
#define C_  64

#define NGROUP 8      // batch groups (8 batches each)
#define GBLK   16     // blocks per group (u-tiles of 16)

typedef unsigned long long ull;

// ---------------- scratch (static device allocations; no cudaMalloc) --------
__device__ float     g_xg   [(size_t)B_ * T_ * G4];   // 512 MB gate preacts
__device__ float     g_hseq [(size_t)B_ * T_ * H_];   // 128 MB layer-0 h sequence / y0
__device__ float     g_hbuf [2][B_ * H_];             // double-buffered h state
__device__ float     g_hfinal[B_ * H_];               // layer-1 final h
__device__ unsigned  g_bar  [NGROUP];                 // per-group barrier counters

// ---------------- helpers ---------------------------------------------------
__device__ __forceinline__ float sigm(float x) { return 1.0f / (1.0f + expf(-x)); }

// packed f32x2 fma: d = a*b + c on both 32-bit lanes
__device__ __forceinline__ ull ffma2(ull a, ull b, ull c) {
    ull d;
    asm("fma.rn.f32x2 %0, %1, %2, %3;" : "=l"(d) : "l"(a), "l"(b), "l"(c));
    return d;
}
__device__ __forceinline__ float hsum2(ull v) {
    union { ull u; float2 f; } cv; cv.u = v;
    return cv.f.x + cv.f.y;
}

// ---------------- init: zero barrier counters + h buffers -------------------
__global__ void init_kernel() {
    int i = blockIdx.x * blockDim.x + threadIdx.x;
    if (i < NGROUP) g_bar[i] = 0u;
    float* hb = &g_hbuf[0][0];
    int n = 2 * B_ * H_;
    for (int j = i; j < n; j += gridDim.x * blockDim.x) hb[j] = 0.0f;
}

// ---------------- phase A: xg = A @ W^T + (bih + bhh) -----------------------
// A: [M x K] row-major (M = B*T), W: [1024 x K] row-major, C = g_xg [M x 1024]
// Tiles: BM=128, BN=128, BK=16, 256 threads, thread tile 8x8, packed-k FFMA2.
#define SPITCH 36     // smem row pitch in floats (stride mod 32 = 4 -> conflict free)

template<int K, int USE_HSEQ>
__global__ void __launch_bounds__(256) sgemm_xg(const float* __restrict__ Ain,
                                                const float* __restrict__ W,
                                                const float* __restrict__ bih,
                                                const float* __restrict__ bhh)
{
    const float* A = USE_HSEQ ? (const float*)g_hseq : Ain;
    const int n0 = blockIdx.x * 128;
    const int m0 = blockIdx.y * 128;

    __shared__ __align__(16) float As[128 * SPITCH];
    __shared__ __align__(16) float Ws[128 * SPITCH];

    const int tid  = threadIdx.x;
    const int tx   = tid & 15;       // -> n = n0 + tx + 16*j
    const int ty   = tid >> 4;       // -> m = m0 + ty + 16*i
    const int lrow = tid >> 2;       // 0..63 load row
    const int lkq  = (tid & 3) * 4;  // k quad within tile

    const float* Ag = A + (size_t)(m0 + lrow) * K + lkq;
    const float* Wg = W + (size_t)(n0 + lrow) * K + lkq;

    ull acc[8][8];
#pragma unroll
    for (int i = 0; i < 8; ++i)
#pragma unroll
        for (int j = 0; j < 8; ++j) acc[i][j] = 0ull;

    // prologue: tile 0 -> smem
    {
        float4 a0 = __ldg((const float4*)Ag);
        float4 a1 = __ldg((const float4*)(Ag + (size_t)64 * K));
        float4 w0 = __ldg((const float4*)Wg);
        float4 w1 = __ldg((const float4*)(Wg + (size_t)64 * K));
        *(float4*)&As[lrow * SPITCH + lkq]        = a0;
        *(float4*)&As[(lrow + 64) * SPITCH + lkq] = a1;
        *(float4*)&Ws[lrow * SPITCH + lkq]        = w0;
        *(float4*)&Ws[(lrow + 64) * SPITCH + lkq] = w1;
    }
    __syncthreads();

    const int NT = K / 16;
    for (int t = 0; t < NT; ++t) {
        float4 na0, na1, nw0, nw1;
        if (t + 1 < NT) {
            const float* Ag2 = Ag + (t + 1) * 16;
            const float* Wg2 = Wg + (t + 1) * 16;
            na0 = __ldg((const float4*)Ag2);
            na1 = __ldg((const float4*)(Ag2 + (size_t)64 * K));
            nw0 = __ldg((const float4*)Wg2);
            nw1 = __ldg((const float4*)(Wg2 + (size_t)64 * K));
        }

#pragma unroll
        for (int q = 0; q < 4; ++q) {
            ull wlo[8], whi[8];
#pragma unroll
            for (int j = 0; j < 8; ++j) {
                const float* wp = &Ws[(tx + 16 * j) * SPITCH + q * 4];
                wlo[j] = *(const ull*)wp;
                whi[j] = *(const ull*)(wp + 2);
            }
#pragma unroll
            for (int i = 0; i < 8; ++i) {
                const float* ap = &As[(ty + 16 * i) * SPITCH + q * 4];
                ull alo = *(const ull*)ap;
                ull ahi = *(const ull*)(ap + 2);
#pragma unroll
                for (int j = 0; j < 8; ++j) {
                    acc[i][j] = ffma2(alo, wlo[j], acc[i][j]);
                    acc[i][j] = ffma2(ahi, whi[j], acc[i][j]);
                }
            }
        }
        __syncthreads();
        if (t + 1 < NT) {
            *(float4*)&As[lrow * SPITCH + lkq]        = na0;
            *(float4*)&As[(lrow + 64) * SPITCH + lkq] = na1;
            *(float4*)&Ws[lrow * SPITCH + lkq]        = nw0;
            *(float4*)&Ws[(lrow + 64) * SPITCH + lkq] = nw1;
            __syncthreads();
        }
    }

    float bb[8];
#pragma unroll
    for (int j = 0; j < 8; ++j) {
        int n = n0 + tx + 16 * j;
        bb[j] = __ldg(&bih[n]) + __ldg(&bhh[n]);
    }
#pragma unroll
    for (int i = 0; i < 8; ++i) {
        size_t m = (size_t)m0 + ty + 16 * i;
        float* op = &g_xg[m * G4 + n0 + tx];
#pragma unroll
        for (int j = 0; j < 8; ++j)
            op[16 * j] = hsum2(acc[i][j]) + bb[j];
    }
}

// ---------------- phase B: persistent recurrent scan ------------------------
// grid 128 blocks, 256 threads. block = (batch group of 8) x (u-tile of 16).
// Thread owns one gate row x one K-quarter (64 weights = 32 packed pairs in regs).
// Packed-k FFMA2 inner loop, 128-bit h reads; one per-group barrier per step.
#define PPITCH 80     // part row pitch (floats) - b stride mod 32 = 16 -> conflict free

template<int FINAL_ONLY>
__global__ void __launch_bounds__(256, 1) recur_kernel(const float* __restrict__ Whh,
                                                       const float* __restrict__ mask)
{
    const int blk = blockIdx.x;
    const int grp = blk >> 4;          // 0..7  batch group
    const int ib  = blk & 15;          // 0..15 u-tile
    const int B0  = grp * 8;
    const int u0  = ib * 16;
    const int tid = threadIdx.x;
    const int u_local = tid & 15;
    const int gate    = (tid >> 4) & 3;
    const int ksub    = tid >> 6;       // 0..3
    const int row     = gate * 256 + u0 + u_local;   // gate row in [0,1024)

    __shared__ __align__(16) float h_sh[8][256];
    __shared__ float part[4][8][PPITCH];   // [ksub][b][gate*16+u]

    // weight slice, packed in k-pairs (stays in regs for all 2048 steps)
    ull w2[32];
    {
        const ulonglong2* wp = (const ulonglong2*)(Whh + (size_t)row * H_ + ksub * 64);
#pragma unroll
        for (int i = 0; i < 16; ++i) {
            ulonglong2 v = __ldg(wp + i);
            w2[2 * i]     = v.x;
            w2[2 * i + 1] = v.y;
        }
    }

    // stage-2 identity (threads < 128 own one (b,u) cell's c-state)
    const int b2 = tid >> 4;   // 0..7  (valid for tid < 128)
    const int u2 = tid & 15;
    float c_state = 0.0f;
    const float* maskp = mask + (size_t)(B0 + b2) * T_;
    const float* xgp   = g_xg + (size_t)(B0 + b2) * T_ * G4 + u0 + u2;

    unsigned target = 0;
    volatile unsigned* barp = (volatile unsigned*)&g_bar[grp];

    for (int step = 0; step < T_; ++step) {
        const int rbuf = step & 1;

        // gate-thread inputs issued early (latency hidden behind the GEMM)
        float x0, x1, x2, x3, mval;
        if (tid < 128) {
            const float* xp = xgp + (size_t)step * G4;
            x0 = __ldg(xp);
            x1 = __ldg(xp + 256);
            x2 = __ldg(xp + 512);
            x3 = __ldg(xp + 768);
            mval = __ldg(maskp + step);
        }

        // load h(t-1) for our 8 batches into smem (L2 reads: other SMs wrote it)
        {
            const float4* src = (const float4*)(g_hbuf[rbuf] + B0 * H_);
            float4* dst = (float4*)&h_sh[0][0];
            dst[tid]       = __ldcg(src + tid);
            dst[tid + 256] = __ldcg(src + tid + 256);
        }
        __syncthreads();

        // GEMM partial: packed-k FFMA2, 128-bit broadcast smem reads
#pragma unroll
        for (int b = 0; b < 8; ++b) {
            const ulonglong2* hp = (const ulonglong2*)&h_sh[b][ksub * 64];
            ull acc = 0ull;
#pragma unroll
            for (int k = 0; k < 16; ++k) {
                ulonglong2 hv = hp[k];
                acc = ffma2(w2[2 * k],     hv.x, acc);
                acc = ffma2(w2[2 * k + 1], hv.y, acc);
            }
            part[ksub][b][gate * 16 + u_local] = hsum2(acc);
        }
        __syncthreads();

        // gate nonlinearities + state update (128 threads: one per (b,u))
        if (tid < 128) {
            float g0 = part[0][b2][ 0 + u2] + part[1][b2][ 0 + u2] + part[2][b2][ 0 + u2] + part[3][b2][ 0 + u2] + x0;
            float g1 = part[0][b2][16 + u2] + part[1][b2][16 + u2] + part[2][b2][16 + u2] + part[3][b2][16 + u2] + x1;
            float g2 = part[0][b2][32 + u2] + part[1][b2][32 + u2] + part[2][b2][32 + u2] + part[3][b2][32 + u2] + x2;
            float g3 = part[0][b2][48 + u2] + part[1][b2][48 + u2] + part[2][b2][48 + u2] + part[3][b2][48 + u2] + x3;
            float c = sigm(g1) * c_state + sigm(g0) * tanhf(g2);
            float h = sigm(g3) * tanhf(c);
            h *= mval; c *= mval;
            c_state = c;
            g_hbuf[rbuf ^ 1][(B0 + b2) * H_ + u0 + u2] = h;
            if (!FINAL_ONLY) {
                g_hseq[((size_t)(B0 + b2) * T_ + step) * H_ + u0 + u2] = h;
            } else if (step == T_ - 1) {
                g_hfinal[(B0 + b2) * H_ + u0 + u2] = h;
            }
        }

        // release + per-group barrier (16 blocks)
        __threadfence();
        __syncthreads();
        target += GBLK;
        if (tid == 0) {
            atomicAdd((unsigned*)&g_bar[grp], 1u);
            while (*barp < target) { }
        }
        __syncthreads();
    }
}

// ---------------- LN + ReLU over layer-0 output (in place) ------------------
__global__ void ln_relu_kernel(const float* __restrict__ g, const float* __restrict__ b)
{
    int row  = blockIdx.x * 8 + (threadIdx.x >> 5);
    int lane = threadIdx.x & 31;
    float* p = g_hseq + (size_t)row * H_;
    float4 v0 = *(float4*)(p + lane * 4);
    float4 v1 = *(float4*)(p + 128 + lane * 4);
    float s = v0.x + v0.y + v0.z + v0.w + v1.x + v1.y + v1.z + v1.w;
    float q = v0.x*v0.x + v0.y*v0.y + v0.z*v0.z + v0.w*v0.w
            + v1.x*v1.x + v1.y*v1.y + v1.z*v1.z + v1.w*v1.w;
#pragma unroll
    for (int o = 16; o; o >>= 1) {
        s += __shfl_xor_sync(0xffffffffu, s, o);
        q += __shfl_xor_sync(0xffffffffu, q, o);
    }
    float mu  = s * (1.0f / 256.0f);
    float var = q * (1.0f / 256.0f) - mu * mu;
    float rs  = rsqrtf(var + 1e-5f);
    int u = lane * 4;
    float4 G0 = *(const float4*)(g + u);       float4 Bb0 = *(const float4*)(b + u);
    float4 G1 = *(const float4*)(g + 128 + u); float4 Bb1 = *(const float4*)(b + 128 + u);
    v0.x = fmaxf(0.0f, (v0.x - mu) * rs * G0.x + Bb0.x);
    v0.y = fmaxf(0.0f, (v0.y - mu) * rs * G0.y + Bb0.y);
    v0.z = fmaxf(0.0f, (v0.z - mu) * rs * G0.z + Bb0.z);
    v0.w = fmaxf(0.0f, (v0.w - mu) * rs * G0.w + Bb0.w);
    v1.x = fmaxf(0.0f, (v1.x - mu) * rs * G1.x + Bb1.x);
    v1.y = fmaxf(0.0f, (v1.y - mu) * rs * G1.y + Bb1.y);
    v1.z = fmaxf(0.0f, (v1.z - mu) * rs * G1.z + Bb1.z);
    v1.w = fmaxf(0.0f, (v1.w - mu) * rs * G1.w + Bb1.w);
    *(float4*)(p + lane * 4)       = v0;
    *(float4*)(p + 128 + lane * 4) = v1;
}

// ---------------- final: LN + ReLU + FC on last-step h of layer 1 -----------
__global__ void final_kernel(const float* __restrict__ lng, const float* __restrict__ lnb,
                             const float* __restrict__ fcW, const float* __restrict__ fcb,
                             float* __restrict__ out)
{
    int b = blockIdx.x;
    int t = threadIdx.x;
    __shared__ float ssum[8], sq[8];
    __shared__ float y[256];
    __shared__ float stats[2];
    float v = g_hfinal[b * H_ + t];
    float s = v, q = v * v;
#pragma unroll
    for (int o = 16; o; o >>= 1) {
        s += __shfl_xor_sync(0xffffffffu, s, o);
        q += __shfl_xor_sync(0xffffffffu, q, o);
    }
    if ((t & 31) == 0) { ssum[t >> 5] = s; sq[t >> 5] = q; }
    __syncthreads();
    if (t == 0) {
        float S = 0.0f, Q = 0.0f;
        for (int i = 0; i < 8; ++i) { S += ssum[i]; Q += sq[i]; }
        float mu  = S * (1.0f / 256.0f);
        float var = Q * (1.0f / 256.0f) - mu * mu;
        stats[0] = mu;
        stats[1] = rsqrtf(var + 1e-5f);
    }
    __syncthreads();
    y[t] = fmaxf(0.0f, (v - stats[0]) * stats[1] * lng[t] + lnb[t]);
    __syncthreads();
    if (t < C_) {
        float a = fcb[t];
        const float* wr = fcW + (size_t)t * H_;
#pragma unroll 8
        for (int u = 0; u < H_; ++u) a = fmaf(y[u], wr[u], a);
        out[b * C_ + t] = a;
    }
}

// ---------------- host entry -------------------------------------------------
extern "C" void kernel_launch(void* const* d_in, const int* in_sizes, int n_in,
                              void* d_out, int out_size)
{
    const float* seq  = (const float*)d_in[0];
    const float* mask = (const float*)d_in[1];
    const float* Wih0 = (const float*)d_in[2];
    const float* Whh0 = (const float*)d_in[3];
    const float* bih0 = (const float*)d_in[4];
    const float* bhh0 = (const float*)d_in[5];
    const float* lng0 = (const float*)d_in[6];
    const float* lnb0 = (const float*)d_in[7];
    const float* Wih1 = (const float*)d_in[8];
    const float* Whh1 = (const float*)d_in[9];
    const float* bih1 = (const float*)d_in[10];
    const float* bhh1 = (const float*)d_in[11];
    const float* lng1 = (const float*)d_in[12];
    const float* lnb1 = (const float*)d_in[13];
    const float* fcW  = (const float*)d_in[14];
    const float* fcb  = (const float*)d_in[15];
    float* out = (float*)d_out;

    const int M = B_ * T_;               // 131072
    dim3 gemm_grid(G4 / 128, M / 128);   // (8, 1024)

    // ---- layer 0 ----
    init_kernel<<<32, 256>>>();
    sgemm_xg<I_, 0><<<gemm_grid, 256>>>(seq, Wih0, bih0, bhh0);
    recur_kernel<0><<<NGROUP * GBLK, 256>>>(Whh0, mask);
    ln_relu_kernel<<<M / 8, 256>>>(lng0, lnb0);

    // ---- layer 1 ----
    init_kernel<<<32, 256>>>();
    sgemm_xg<H_, 1><<<gemm_grid, 256>>>(nullptr, Wih1, bih1, bhh1);
    recur_kernel<1><<<NGROUP * GBLK, 256>>>(Whh1, mask);

    // ---- head ----
    final_kernel<<<B_, 256>>>(lng1, lnb1, fcW, fcb, out);
}